// round 14
// baseline (speedup 1.0000x reference)
#include <cuda_runtime.h>
#include <cstdint>

// out[row, :] = features[rules[row], :]
// features: [N_ACTIVE=200000, C=64] fp32   (51.2 MB — resident in 126 MB L2)
// rules:    [N_ROWS=524288] int32
// out:      [N_ROWS, 64] fp32
//
// R13 -> R14: R13 (float8, ILP=2) won on instruction count; still latency-bound
// (DRAM 61%, issue 10%). Raise in-flight bytes/thread without collapsing occ:
//   ILP=3 float8 -> 96B in flight per thread, est ~40 regs -> ~75% occ
//   => effective in-flight ~1.4x vs R13. Index/gather/store phases stay
//   front-batched (3 independent arms, no loop carry).

#define ILP 3

__device__ __forceinline__ void ldg256(const float* a, float* v) {
    asm volatile("ld.global.nc.v8.f32 {%0,%1,%2,%3,%4,%5,%6,%7}, [%8];"
                 : "=f"(v[0]), "=f"(v[1]), "=f"(v[2]), "=f"(v[3]),
                   "=f"(v[4]), "=f"(v[5]), "=f"(v[6]), "=f"(v[7])
                 : "l"(a));
}
__device__ __forceinline__ void stg256_cs(float* a, const float* v) {
    asm volatile("st.global.cs.v8.f32 [%0], {%1,%2,%3,%4,%5,%6,%7,%8};"
                 :: "l"(a),
                    "f"(v[0]), "f"(v[1]), "f"(v[2]), "f"(v[3]),
                    "f"(v[4]), "f"(v[5]), "f"(v[6]), "f"(v[7])
                 : "memory");
}

__global__ void __launch_bounds__(256)
bl_gather_kernel(const float* __restrict__ feat,
                 const int* __restrict__ rules,
                 float* __restrict__ out,
                 int total_vec8)  // n_rows * 8
{
    const int tid = blockIdx.x * blockDim.x + threadIdx.x;
    const int nth = gridDim.x * blockDim.x;

    int   idx[ILP];
    int   r[ILP];
    float v[ILP][8];

    // index loads: coalesced, broadcast within 8-lane groups (4 rows/warp/arm)
    #pragma unroll
    for (int i = 0; i < ILP; i++) {
        idx[i] = tid + i * nth;
        int row = idx[i] >> 3;              // 8 float8 per row
        r[i] = (idx[i] < total_vec8) ? __ldg(&rules[row]) : 0;
    }
    // gather: ILP independent 256-bit loads in flight
    #pragma unroll
    for (int i = 0; i < ILP; i++) {
        int c8 = idx[i] & 7;
        if (idx[i] < total_vec8)
            ldg256(feat + ((long long)r[i] * 64 + c8 * 8), v[i]);
    }
    // store: 256-bit streaming (evict-first) stores, fully coalesced;
    // keeps the feature table L2-resident (verified R4/R13)
    #pragma unroll
    for (int i = 0; i < ILP; i++) {
        if (idx[i] < total_vec8)
            stg256_cs(out + (long long)idx[i] * 8, v[i]);
    }
}

extern "C" void kernel_launch(void* const* d_in, const int* in_sizes, int n_in,
                              void* d_out, int out_size)
{
    const float* feat  = (const float*)d_in[0];   // features [nActive, 64] fp32
    const int*   rules = (const int*)d_in[1];     // rules [n_rows] int32

    int n_rows     = in_sizes[1];          // 524288
    int total_vec8 = n_rows * 8;           // 4,194,304

    float* out = (float*)d_out;

    const int threads = 256;
    int blocks = (total_vec8 + threads * ILP - 1) / (threads * ILP);  // 5462
    bl_gather_kernel<<<blocks, threads>>>(feat, rules, out, total_vec8);
}

// round 17
// speedup vs baseline: 1.1069x; 1.1069x over previous
#include <cuda_runtime.h>
#include <cstdint>

// out[row, :] = features[rules[row], :]
// features: [N_ACTIVE=200000, C=64] fp32   (51.2 MB — resident in 126 MB L2)
// rules:    [N_ROWS=524288] int32
// out:      [N_ROWS, 64] fp32
//
// R14 -> R15: revert ILP=3 (occupancy loss ate the gain — 3rd confirmation).
// Keep R13's winning shape (float8 x2, ~32 regs, 256 thr) but fuse both arms
// onto ONE row: 4 threads per row, thread q handles c8 = q and q+4.
//   - 1 index LDG per thread instead of 2 (6 -> 5 mem instrs, one dep arm)
//   - gathers stay optimal: per arm, lanes 4q..4q+3 cover 128B contiguous of
//     a row -> 8 lines per warp LDG.256 (identical to R13; unlike R8's
//     64B-strided lanes which inflated wavefronts 4x)
//   - stores: 8 x 128B chunks per STG.256 (same sector count as R13)
//   - st.global.cs retained: feature table stays L2-resident (verified R4/R13)

__device__ __forceinline__ void ldg256(const float* a, float* v) {
    asm volatile("ld.global.nc.v8.f32 {%0,%1,%2,%3,%4,%5,%6,%7}, [%8];"
                 : "=f"(v[0]), "=f"(v[1]), "=f"(v[2]), "=f"(v[3]),
                   "=f"(v[4]), "=f"(v[5]), "=f"(v[6]), "=f"(v[7])
                 : "l"(a));
}
__device__ __forceinline__ void stg256_cs(float* a, const float* v) {
    asm volatile("st.global.cs.v8.f32 [%0], {%1,%2,%3,%4,%5,%6,%7,%8};"
                 :: "l"(a),
                    "f"(v[0]), "f"(v[1]), "f"(v[2]), "f"(v[3]),
                    "f"(v[4]), "f"(v[5]), "f"(v[6]), "f"(v[7])
                 : "memory");
}

__global__ void __launch_bounds__(256)
bl_gather_kernel(const float* __restrict__ feat,
                 const int* __restrict__ rules,
                 float* __restrict__ out,
                 int n_rows)
{
    const int tid = blockIdx.x * blockDim.x + threadIdx.x;
    const int row = tid >> 2;        // 4 threads per row
    const int q   = tid & 3;         // which 128B half-chunk pair

    if (row >= n_rows) return;

    const int r = __ldg(&rules[row]);            // single index load
    const float* src = feat + (long long)r * 64;

    float v0[8], v1[8];
    ldg256(src + q * 8,      v0);    // c8 = q    (first  half-row, 128B group)
    ldg256(src + q * 8 + 32, v1);    // c8 = q+4  (second half-row, 128B group)

    float* dst = out + (long long)row * 64;
    stg256_cs(dst + q * 8,      v0);
    stg256_cs(dst + q * 8 + 32, v1);
}

extern "C" void kernel_launch(void* const* d_in, const int* in_sizes, int n_in,
                              void* d_out, int out_size)
{
    const float* feat  = (const float*)d_in[0];   // features [nActive, 64] fp32
    const int*   rules = (const int*)d_in[1];     // rules [n_rows] int32

    int n_rows = in_sizes[1];                     // 524288
    float* out = (float*)d_out;

    const int threads = 256;
    int total_threads = n_rows * 4;               // 2,097,152
    int blocks = (total_threads + threads - 1) / threads;   // 8192
    bl_gather_kernel<<<blocks, threads>>>(feat, rules, out, n_rows);
}